// round 14
// baseline (speedup 1.0000x reference)
#include <cuda_runtime.h>
#include <cuda_fp16.h>
#include <math.h>
#include <stdint.h>

// Problem shape (fixed by setup_inputs)
constexpr int   NN = 100000;
constexpr int   FF = 500;
constexpr int   HH = 64;
constexpr int   CC = 40;
constexpr int   EE = 3200000;
constexpr float ALPHA = 0.1f;
constexpr float OMA   = 0.9f;   // 1 - alpha
constexpr int   SCAN_B = (NN + 255) / 256;  // 391 scan blocks

// ---- scratch (static __device__ arrays; zero-initialized at module load) ----
__device__ int     g_w64;           // 1 if edge_index is int64, 0 if int32
__device__ int     g_degi[NN];      // ALWAYS zero at kernel_launch entry
                                    // (module-load init; k_scan3 self-cleans)
__device__ float   g_dinv[NN];
__device__ float   g_selfc[NN];
__device__ int     g_ptr[NN + 1];   // CSR row pointers (by dst)
__device__ int     g_cursor[NN];
__device__ int     g_bsum[SCAN_B];
__device__ int     g_boff[SCAN_B];
__device__ int2    g_csr[EE];       // (src, half2(w,w) bits)
__device__ __half  g_h1h[(size_t)NN * HH];   // fp16 hidden
__device__ float4  g_h0[(size_t)NN * 10];    // fp32 teleport anchor
__device__ uint4   g_h16A[(size_t)NN * 5];   // fp16 h (40 halfs = 5 uint4)
__device__ uint4   g_h16B[(size_t)NN * 5];

// ---------------- dtype sniff (1 block, 64 probes) ----------------
__global__ void k_sniff(const unsigned long long* __restrict__ ei) {
    __shared__ int anybad[2];
    unsigned long long v = ei[threadIdx.x];
    unsigned bad = __ballot_sync(0xFFFFFFFFu, v >= (unsigned long long)NN);
    anybad[threadIdx.x >> 5] = 0;
    __syncwarp();
    if (bad) anybad[threadIdx.x >> 5] = 1;
    __syncthreads();
    if (threadIdx.x == 0) g_w64 = !(anybad[0] | anybad[1]);
}

// ---------------- degree count (2 edges/thread, vector loads) ----------------
__global__ void k_deg_count(const void* __restrict__ eiv) {
    int t = blockIdx.x * blockDim.x + threadIdx.x;
    int e = t * 2;
    if (e >= EE) return;
    int d0, d1;
    if (g_w64) {
        ulonglong2 p = *(const ulonglong2*)((const unsigned long long*)eiv + EE + e);
        d0 = (int)p.x; d1 = (int)p.y;
    } else {
        int2 p = *(const int2*)((const int*)eiv + EE + e);
        d0 = p.x; d1 = p.y;
    }
    atomicAdd(&g_degi[d0], 1);
    atomicAdd(&g_degi[d1], 1);
}

// ---------------- scan1 (+ dinv/selfc fused) ----------------
__global__ void k_scan1() {
    __shared__ int sm[256];
    int i = blockIdx.x * 256 + threadIdx.x;
    int v = (i < NN) ? g_degi[i] : 0;
    if (i < NN) {
        float deg = (float)(v + 1);        // + self-loop
        g_dinv[i]  = rsqrtf(deg);
        g_selfc[i] = OMA / deg;
    }
    sm[threadIdx.x] = v;
    __syncthreads();
#pragma unroll
    for (int off = 1; off < 256; off <<= 1) {
        int t = (threadIdx.x >= off) ? sm[threadIdx.x - off] : 0;
        __syncthreads();
        sm[threadIdx.x] += t;
        __syncthreads();
    }
    if (i < NN) g_ptr[i] = sm[threadIdx.x] - v;
    if (threadIdx.x == 255) g_bsum[blockIdx.x] = sm[255];
}

__global__ void k_scan2() {
    __shared__ int sm[512];
    int t = threadIdx.x;
    sm[t] = (t < SCAN_B) ? g_bsum[t] : 0;
    __syncthreads();
#pragma unroll
    for (int off = 1; off < 512; off <<= 1) {
        int v = (t >= off) ? sm[t - off] : 0;
        __syncthreads();
        sm[t] += v;
        __syncthreads();
    }
    if (t < SCAN_B) g_boff[t] = sm[t] - g_bsum[t];
}

__global__ void k_scan3() {
    int i = blockIdx.x * 256 + threadIdx.x;
    if (i < NN) {
        int p = g_ptr[i] + g_boff[blockIdx.x];
        g_ptr[i] = p;
        g_cursor[i] = p;
        g_degi[i] = 0;        // self-clean for the next call
    }
    if (i == 0) g_ptr[NN] = EE;
}

// ---------------- CSR fill (2 edges/thread, half2(w,w) weight) ----------------
__global__ void k_fill(const void* __restrict__ eiv) {
    int t = blockIdx.x * blockDim.x + threadIdx.x;
    int e = t * 2;
    if (e >= EE) return;
    int s0, s1, d0, d1;
    if (g_w64) {
        const unsigned long long* p = (const unsigned long long*)eiv;
        ulonglong2 sp = *(const ulonglong2*)(p + e);
        ulonglong2 dp = *(const ulonglong2*)(p + EE + e);
        s0 = (int)sp.x; s1 = (int)sp.y;
        d0 = (int)dp.x; d1 = (int)dp.y;
    } else {
        const int* p = (const int*)eiv;
        int2 sp = *(const int2*)(p + e);
        int2 dp = *(const int2*)(p + EE + e);
        s0 = sp.x; s1 = sp.y;
        d0 = dp.x; d1 = dp.y;
    }
    int pos0 = atomicAdd(&g_cursor[d0], 1);
    __half2 w0 = __float2half2_rn(OMA * g_dinv[s0] * g_dinv[d0]);
    g_csr[pos0] = make_int2(s0, *(int*)&w0);
    int pos1 = atomicAdd(&g_cursor[d1], 1);
    __half2 w1 = __float2half2_rn(OMA * g_dinv[s1] * g_dinv[d1]);
    g_csr[pos1] = make_int2(s1, *(int*)&w1);
}

// ---------------- common mma helpers ----------------
__device__ __forceinline__ unsigned bf2(float lo, float hi) {
    unsigned r;
    asm("cvt.rn.bf16x2.f32 %0, %1, %2;" : "=r"(r) : "f"(hi), "f"(lo));
    return r;
}
__device__ __forceinline__ uint32_t smem_u32(const void* p) {
    uint32_t a;
    asm("{ .reg .u64 t; cvta.to.shared.u64 t, %1; cvt.u32.u64 %0, t; }" : "=r"(a) : "l"(p));
    return a;
}
__device__ __forceinline__ void ldm_x4(uint32_t& r0, uint32_t& r1, uint32_t& r2, uint32_t& r3,
                                       uint32_t addr) {
    asm volatile("ldmatrix.sync.aligned.m8n8.x4.shared.b16 {%0,%1,%2,%3}, [%4];"
                 : "=r"(r0), "=r"(r1), "=r"(r2), "=r"(r3) : "r"(addr));
}
__device__ __forceinline__ void ldm_x4_t(uint32_t& r0, uint32_t& r1, uint32_t& r2, uint32_t& r3,
                                         uint32_t addr) {
    asm volatile("ldmatrix.sync.aligned.m8n8.x4.trans.shared.b16 {%0,%1,%2,%3}, [%4];"
                 : "=r"(r0), "=r"(r1), "=r"(r2), "=r"(r3) : "r"(addr));
}
__device__ __forceinline__ void ldm_x2_t(uint32_t& r0, uint32_t& r1, uint32_t addr) {
    asm volatile("ldmatrix.sync.aligned.m8n8.x2.trans.shared.b16 {%0,%1}, [%2];"
                 : "=r"(r0), "=r"(r1) : "r"(addr));
}
__device__ __forceinline__ void mma_bf16(float c[4], const uint32_t a[4], const uint32_t b[2]) {
    asm("mma.sync.aligned.m16n8k16.row.col.f32.bf16.bf16.f32 "
        "{%0,%1,%2,%3}, {%4,%5,%6,%7}, {%8,%9}, {%0,%1,%2,%3};"
        : "+f"(c[0]), "+f"(c[1]), "+f"(c[2]), "+f"(c[3])
        : "r"(a[0]), "r"(a[1]), "r"(a[2]), "r"(a[3]), "r"(b[0]), "r"(b[1]));
}
__device__ __forceinline__ void mma_f16(float c[4], const uint32_t a[4], const uint32_t b[2]) {
    asm("mma.sync.aligned.m16n8k16.row.col.f32.f16.f16.f32 "
        "{%0,%1,%2,%3}, {%4,%5,%6,%7}, {%8,%9}, {%0,%1,%2,%3};"
        : "+f"(c[0]), "+f"(c[1]), "+f"(c[2]), "+f"(c[3])
        : "r"(a[0]), "r"(a[1]), "r"(a[2]), "r"(a[3]), "r"(b[0]), "r"(b[1]));
}
__device__ __forceinline__ void hfma2(unsigned& acc, unsigned a, unsigned b) {
    asm("fma.rn.f16x2 %0, %1, %2, %0;" : "+r"(acc) : "r"(a), "r"(b));
}

// ---------------- GEMM1 (bf16 mma, double-buffered) -> fp16 h1 ----------------
__global__ void k_gemm1(const float* __restrict__ x,
                        const float* __restrict__ W1,
                        const float* __restrict__ b1) {
    __shared__ uint4 As4[2][512];
    __shared__ uint4 Bs4[2][256];
    __shared__ float b1s[64];
    const int tid  = threadIdx.x;
    const int lane = tid & 31;
    const int wid  = tid >> 5;
    const int wm   = wid >> 1;
    const int wn   = wid & 1;
    const int g    = lane >> 2;
    const int kt   = lane & 3;
    const int r0   = blockIdx.x * 128;
    if (tid < 64) b1s[tid] = b1[tid];

    const int amA[2]  = { (tid * 2) >> 2, (tid * 2 + 1) >> 2 };
    const int accA[2] = { (tid * 2) & 3,  (tid * 2 + 1) & 3 };
    const int bk  = tid >> 3;
    const int bcc = tid & 7;

    float c[2][4][4];
#pragma unroll
    for (int mt = 0; mt < 2; mt++)
#pragma unroll
        for (int nt = 0; nt < 4; nt++)
#pragma unroll
            for (int i = 0; i < 4; i++) c[mt][nt][i] = 0.0f;

    float4 pa[2][2];
    float4 pb[2];

    auto load_chunk = [&](int kb) {
#pragma unroll
        for (int j = 0; j < 2; j++) {
            int gr = r0 + amA[j];
            int gk = kb + accA[j] * 8;
            pa[j][0] = make_float4(0.f, 0.f, 0.f, 0.f);
            pa[j][1] = make_float4(0.f, 0.f, 0.f, 0.f);
            if (gr < NN) {
                const float* xp = &x[(size_t)gr * FF + gk];
                if (gk + 4 <= FF) pa[j][0] = *(const float4*)xp;
                if (gk + 8 <= FF) pa[j][1] = *(const float4*)(xp + 4);
            }
        }
        int gk = kb + bk;
        pb[0] = make_float4(0.f, 0.f, 0.f, 0.f);
        pb[1] = make_float4(0.f, 0.f, 0.f, 0.f);
        if (gk < FF) {
            const float* wp = &W1[(size_t)gk * HH + bcc * 8];
            pb[0] = *(const float4*)wp;
            pb[1] = *(const float4*)(wp + 4);
        }
    };
    auto store_chunk = [&](int buf) {
#pragma unroll
        for (int j = 0; j < 2; j++) {
            uint4 u;
            u.x = bf2(pa[j][0].x, pa[j][0].y);
            u.y = bf2(pa[j][0].z, pa[j][0].w);
            u.z = bf2(pa[j][1].x, pa[j][1].y);
            u.w = bf2(pa[j][1].z, pa[j][1].w);
            As4[buf][amA[j] * 4 + (accA[j] ^ ((amA[j] >> 1) & 3))] = u;
        }
        uint4 u;
        u.x = bf2(pb[0].x, pb[0].y);
        u.y = bf2(pb[0].z, pb[0].w);
        u.z = bf2(pb[1].x, pb[1].y);
        u.w = bf2(pb[1].z, pb[1].w);
        Bs4[buf][bk * 8 + (bcc ^ (bk & 7))] = u;
    };

    load_chunk(0);
    store_chunk(0);
    __syncthreads();

    for (int kb = 0; kb < 512; kb += 32) {
        const int buf = (kb >> 5) & 1;
        const bool has_next = (kb + 32 < 512);
        if (has_next) load_chunk(kb + 32);

        const uint32_t As_base = smem_u32(As4[buf]);
        const uint32_t Bs_base = smem_u32(Bs4[buf]);
#pragma unroll
        for (int ks = 0; ks < 32; ks += 16) {
            uint32_t a[2][4];
#pragma unroll
            for (int mt = 0; mt < 2; mt++) {
                int m  = wm * 32 + mt * 16 + (lane & 15);
                int cA = (ks >> 3) + (lane >> 4);
                uint32_t addr = As_base + m * 64 + ((cA ^ ((m >> 1) & 3)) << 4);
                ldm_x4(a[mt][0], a[mt][1], a[mt][2], a[mt][3], addr);
            }
            uint32_t b[4][2];
#pragma unroll
            for (int p = 0; p < 2; p++) {
                int k  = ks + (lane & 15);
                int cB = wn * 4 + 2 * p + (lane >> 4);
                uint32_t addr = Bs_base + k * 128 + ((cB ^ (k & 7)) << 4);
                ldm_x4_t(b[2 * p][0], b[2 * p][1], b[2 * p + 1][0], b[2 * p + 1][1], addr);
            }
#pragma unroll
            for (int mt = 0; mt < 2; mt++)
#pragma unroll
                for (int nt = 0; nt < 4; nt++)
                    mma_bf16(c[mt][nt], a[mt], b[nt]);
        }
        if (has_next) {
            store_chunk(buf ^ 1);
            __syncthreads();
        }
    }
#pragma unroll
    for (int mt = 0; mt < 2; mt++) {
        int row = r0 + wm * 32 + mt * 16 + g;
#pragma unroll
        for (int nt = 0; nt < 4; nt++) {
            int col = wn * 32 + nt * 8 + 2 * kt;
            if (row < NN) {
                __half2 v = __float22half2_rn(make_float2(fmaxf(c[mt][nt][0] + b1s[col], 0.f),
                                                          fmaxf(c[mt][nt][1] + b1s[col + 1], 0.f)));
                *(__half2*)&g_h1h[(size_t)row * HH + col] = v;
            }
            if (row + 8 < NN) {
                __half2 v = __float22half2_rn(make_float2(fmaxf(c[mt][nt][2] + b1s[col], 0.f),
                                                          fmaxf(c[mt][nt][3] + b1s[col + 1], 0.f)));
                *(__half2*)&g_h1h[(size_t)(row + 8) * HH + col] = v;
            }
        }
    }
}

// ---------------- GEMM2 (fp16 tensor cores) -> h16A + h0 ----------------
__global__ void k_gemm2(const float* __restrict__ W2,
                        const float* __restrict__ b2) {
    __shared__ uint4  h1s4[1024];
    __shared__ __half Bs[64 * 40];
    __shared__ float  b2s[40];
    const int tid  = threadIdx.x;
    const int lane = tid & 31;
    const int wid  = tid >> 5;
    const int g    = lane >> 2;
    const int kt   = lane & 3;
    const int rb   = blockIdx.x * 128;

#pragma unroll
    for (int j = 0; j < 5; j++) {
        int idx = tid + j * 128;
        int k   = idx / 10;
        int cg  = idx % 10;
        float4 v = *(const float4*)&W2[(size_t)k * CC + cg * 4];
        __half2 h0 = __float22half2_rn(make_float2(v.x, v.y));
        __half2 h1 = __float22half2_rn(make_float2(v.z, v.w));
        uint2 u;
        u.x = *(unsigned*)&h0;
        u.y = *(unsigned*)&h1;
        *(uint2*)&Bs[k * 40 + cg * 4] = u;
    }
    if (tid < 40) b2s[tid] = b2[tid];

#pragma unroll
    for (int j = 0; j < 8; j++) {
        int idx = tid + j * 128;
        int r   = idx >> 3;
        int cc  = idx & 7;
        int gr  = rb + r;
        uint4 v = make_uint4(0, 0, 0, 0);
        if (gr < NN) v = *(const uint4*)&g_h1h[(size_t)gr * HH + cc * 8];
        h1s4[r * 8 + (cc ^ (r & 7))] = v;
    }
    __syncthreads();

    const uint32_t A_base = smem_u32(h1s4);
    const uint32_t B_base = smem_u32(Bs);

    float c[2][5][4];
#pragma unroll
    for (int mt = 0; mt < 2; mt++)
#pragma unroll
        for (int nt = 0; nt < 5; nt++)
#pragma unroll
            for (int i = 0; i < 4; i++) c[mt][nt][i] = 0.0f;

#pragma unroll
    for (int ks = 0; ks < 64; ks += 16) {
        uint32_t a[2][4];
#pragma unroll
        for (int mt = 0; mt < 2; mt++) {
            int m  = wid * 32 + mt * 16 + (lane & 15);
            int cA = (ks >> 3) + (lane >> 4);
            uint32_t addr = A_base + m * 128 + ((cA ^ (m & 7)) << 4);
            ldm_x4(a[mt][0], a[mt][1], a[mt][2], a[mt][3], addr);
        }
        uint32_t b[5][2];
#pragma unroll
        for (int p = 0; p < 2; p++) {
            int k = ks + (lane & 15);
            int n = 2 * p * 8 + (lane >> 4) * 8;
            uint32_t addr = B_base + (k * 40 + n) * 2;
            ldm_x4_t(b[2 * p][0], b[2 * p][1], b[2 * p + 1][0], b[2 * p + 1][1], addr);
        }
        {
            int k = ks + (lane & 15);
            uint32_t addr = B_base + (k * 40 + 32) * 2;
            ldm_x2_t(b[4][0], b[4][1], addr);
        }
#pragma unroll
        for (int mt = 0; mt < 2; mt++)
#pragma unroll
            for (int nt = 0; nt < 5; nt++)
                mma_f16(c[mt][nt], a[mt], b[nt]);
    }

    float*   h0f  = (float*)g_h0;
    __half2* h16  = (__half2*)g_h16A;
#pragma unroll
    for (int mt = 0; mt < 2; mt++) {
        int row0 = rb + wid * 32 + mt * 16 + g;
#pragma unroll
        for (int nt = 0; nt < 5; nt++) {
            int col = nt * 8 + 2 * kt;
            float bx = b2s[col], by = b2s[col + 1];
            if (row0 < NN) {
                float2 v = make_float2(c[mt][nt][0] + bx, c[mt][nt][1] + by);
                *(float2*)&h0f[(size_t)row0 * CC + col] = v;
                h16[(size_t)row0 * 20 + col / 2] = __float22half2_rn(v);
            }
            if (row0 + 8 < NN) {
                float2 v = make_float2(c[mt][nt][2] + bx, c[mt][nt][3] + by);
                *(float2*)&h0f[(size_t)(row0 + 8) * CC + col] = v;
                h16[(size_t)(row0 + 8) * 20 + col / 2] = __float22half2_rn(v);
            }
        }
    }
}

// ---------------- propagation: counted loops, 4-edge unrolled HFMA2 blocks ----------------
__global__ void k_prop(int parity) {
    const uint4* __restrict__ cur = parity ? g_h16B : g_h16A;
    uint4*       __restrict__ nw  = parity ? g_h16A : g_h16B;
    int wid = (blockIdx.x * blockDim.x + threadIdx.x) >> 5;
    if (wid >= NN) return;
    int lane = threadIdx.x & 31;
    int g    = lane / 5;          // 0..6 (6 => idle lanes 30,31)
    int c    = lane - g * 5;      // 0..4

    int beg = g_ptr[wid];
    int end = g_ptr[wid + 1];

    float f[8];
#pragma unroll
    for (int j = 0; j < 8; j++) f[j] = 0.f;

    if (g < 6) {
        int e = beg + g;
        int n = (e < end) ? ((end - e) + 5) / 6 : 0;   // edges for this lane group
        // fast path: fully unrolled 4-edge blocks, no per-edge branches.
        // ptxas front-batches the 4 CSR loads (MLP=4) and the 4 gathers.
        while (n >= 4) {
            unsigned a0 = 0, a1 = 0, a2 = 0, a3 = 0;
#pragma unroll
            for (int i = 0; i < 4; i++) {
                int2  sw = g_csr[e + 6 * i];
                uint4 v  = cur[(size_t)sw.x * 5 + c];
                unsigned ww = (unsigned)sw.y;       // half2(w,w)
                hfma2(a0, ww, v.x);
                hfma2(a1, ww, v.y);
                hfma2(a2, ww, v.z);
                hfma2(a3, ww, v.w);
            }
            e += 24; n -= 4;
            float2 p;
            p = __half22float2(*(__half2*)&a0); f[0] += p.x; f[1] += p.y;
            p = __half22float2(*(__half2*)&a1); f[2] += p.x; f[3] += p.y;
            p = __half22float2(*(__half2*)&a2); f[4] += p.x; f[5] += p.y;
            p = __half22float2(*(__half2*)&a3); f[6] += p.x; f[7] += p.y;
        }
        // tail: up to 3 edges
        if (n > 0) {
            unsigned a0 = 0, a1 = 0, a2 = 0, a3 = 0;
#pragma unroll 1
            for (; n > 0; n--, e += 6) {
                int2  sw = g_csr[e];
                uint4 v  = cur[(size_t)sw.x * 5 + c];
                unsigned ww = (unsigned)sw.y;
                hfma2(a0, ww, v.x);
                hfma2(a1, ww, v.y);
                hfma2(a2, ww, v.z);
                hfma2(a3, ww, v.w);
            }
            float2 p;
            p = __half22float2(*(__half2*)&a0); f[0] += p.x; f[1] += p.y;
            p = __half22float2(*(__half2*)&a1); f[2] += p.x; f[3] += p.y;
            p = __half22float2(*(__half2*)&a2); f[4] += p.x; f[5] += p.y;
            p = __half22float2(*(__half2*)&a3); f[6] += p.x; f[7] += p.y;
        }
    }
    const unsigned FULL = 0xFFFFFFFFu;
#pragma unroll
    for (int j = 0; j < 8; j++) {
        float t = __shfl_down_sync(FULL, f[j], 15);
        f[j] += t;
        float t1 = __shfl_down_sync(FULL, f[j], 5);
        float t2 = __shfl_down_sync(FULL, f[j], 10);
        f[j] += t1 + t2;
    }

    if (lane < 5) {
        size_t idx = (size_t)wid * 5 + lane;
        float  sc  = g_selfc[wid];
        uint4  cs  = cur[idx];
        float4 h0a = g_h0[(size_t)wid * 10 + lane * 2 + 0];
        float4 h0b = g_h0[(size_t)wid * 10 + lane * 2 + 1];
        float2 q;
        q = __half22float2(*(__half2*)&cs.x);
        float r0 = f[0] + fmaf(sc, q.x, ALPHA * h0a.x);
        float r1 = f[1] + fmaf(sc, q.y, ALPHA * h0a.y);
        q = __half22float2(*(__half2*)&cs.y);
        float r2 = f[2] + fmaf(sc, q.x, ALPHA * h0a.z);
        float r3 = f[3] + fmaf(sc, q.y, ALPHA * h0a.w);
        q = __half22float2(*(__half2*)&cs.z);
        float r4 = f[4] + fmaf(sc, q.x, ALPHA * h0b.x);
        float r5 = f[5] + fmaf(sc, q.y, ALPHA * h0b.y);
        q = __half22float2(*(__half2*)&cs.w);
        float r6 = f[6] + fmaf(sc, q.x, ALPHA * h0b.z);
        float r7 = f[7] + fmaf(sc, q.y, ALPHA * h0b.w);
        __half2 p0 = __float22half2_rn(make_float2(r0, r1));
        __half2 p1 = __float22half2_rn(make_float2(r2, r3));
        __half2 p2 = __float22half2_rn(make_float2(r4, r5));
        __half2 p3 = __float22half2_rn(make_float2(r6, r7));
        uint4 u;
        u.x = *(unsigned*)&p0; u.y = *(unsigned*)&p1;
        u.z = *(unsigned*)&p2; u.w = *(unsigned*)&p3;
        nw[idx] = u;
    }
}

// ---------------- log_softmax over C=40 (fp16 input), warp per row ----------------
__global__ void k_logsoftmax(float* __restrict__ out) {
    int warp = threadIdx.x >> 5;
    int lane = threadIdx.x & 31;
    int row  = blockIdx.x * 4 + warp;
    if (row >= NN) return;
    const __half2* h = (const __half2*)g_h16A + (size_t)row * 20;
    float2 p = make_float2(-INFINITY, -INFINITY);
    if (lane < 20) p = __half22float2(h[lane]);
    float m = fmaxf(p.x, p.y);
#pragma unroll
    for (int off = 16; off > 0; off >>= 1)
        m = fmaxf(m, __shfl_xor_sync(0xFFFFFFFFu, m, off));
    float s = (lane < 20) ? (expf(p.x - m) + expf(p.y - m)) : 0.0f;
#pragma unroll
    for (int off = 16; off > 0; off >>= 1)
        s += __shfl_xor_sync(0xFFFFFFFFu, s, off);
    float ls = logf(s);
    if (lane < 20) {
        out[(size_t)row * CC + lane * 2 + 0] = p.x - m - ls;
        out[(size_t)row * CC + lane * 2 + 1] = p.y - m - ls;
    }
}

// ---------------- launch ----------------
extern "C" void kernel_launch(void* const* d_in, const int* in_sizes, int n_in,
                              void* d_out, int out_size) {
    const float* x  = (const float*)d_in[0];
    const float* W1 = (const float*)d_in[1];
    const float* b1 = (const float*)d_in[2];
    const float* W2 = (const float*)d_in[3];
    const float* b2 = (const float*)d_in[4];
    const void*  ei = d_in[5];
    float* out = (float*)d_out;

    const int TB  = 256;
    const int gE2 = (EE / 2 + TB - 1) / TB;   // 6250 (2 edges/thread)
    const int gP  = (NN + 7) / 8;             // 8 warps per block

    // g_degi enters every call zeroed (module init / k_scan3 self-clean).
    k_sniff<<<1, 64>>>((const unsigned long long*)ei);        // 0
    k_deg_count<<<gE2, TB>>>(ei);                             // 1
    k_scan1<<<SCAN_B, 256>>>();                               // 2
    k_gemm1<<<(NN + 127) / 128, 256>>>(x, W1, b1);            // 3 (profiled)
    k_scan2<<<1, 512>>>();
    k_scan3<<<SCAN_B, 256>>>();
    k_fill<<<gE2, TB>>>(ei);
    k_gemm2<<<(NN + 127) / 128, 128>>>(W2, b2);

    // K=10 propagation steps (ping-pong; final lands in h16A)
    for (int k = 0; k < 10; k++)
        k_prop<<<gP, TB>>>(k & 1);

    // output
    k_logsoftmax<<<(NN + 3) / 4, 128>>>(out);
}

// round 15
// speedup vs baseline: 1.0935x; 1.0935x over previous
#include <cuda_runtime.h>
#include <cuda_fp16.h>
#include <math.h>
#include <stdint.h>

// Problem shape (fixed by setup_inputs)
constexpr int   NN = 100000;
constexpr int   FF = 500;
constexpr int   HH = 64;
constexpr int   CC = 40;
constexpr int   EE = 3200000;
constexpr float ALPHA = 0.1f;
constexpr float OMA   = 0.9f;   // 1 - alpha
constexpr int   SCAN_B = (NN + 255) / 256;  // 391 scan blocks

// ---- scratch (static __device__ arrays; zero-initialized at module load) ----
__device__ int     g_w64;           // 1 if edge_index is int64, 0 if int32
__device__ int     g_degi[NN];      // ALWAYS zero at kernel_launch entry
                                    // (module-load init; k_scan3 self-cleans)
__device__ float   g_dinv[NN];
__device__ float   g_selfc[NN];
__device__ int     g_ptr[NN + 1];   // CSR row pointers (by dst)
__device__ int     g_cursor[NN];
__device__ int     g_bsum[SCAN_B];
__device__ int     g_boff[SCAN_B];
__device__ int2    g_csr[EE];       // (src, half2(w,w) bits)
__device__ __half  g_h1h[(size_t)NN * HH];   // fp16 hidden
__device__ float4  g_h0[(size_t)NN * 10];    // fp32 teleport anchor
__device__ uint4   g_h16A[(size_t)NN * 5];   // fp16 h (40 halfs = 5 uint4)
__device__ uint4   g_h16B[(size_t)NN * 5];

// ---------------- dtype sniff (1 block, 64 probes) ----------------
__global__ void k_sniff(const unsigned long long* __restrict__ ei) {
    __shared__ int anybad[2];
    unsigned long long v = ei[threadIdx.x];
    unsigned bad = __ballot_sync(0xFFFFFFFFu, v >= (unsigned long long)NN);
    anybad[threadIdx.x >> 5] = 0;
    __syncwarp();
    if (bad) anybad[threadIdx.x >> 5] = 1;
    __syncthreads();
    if (threadIdx.x == 0) g_w64 = !(anybad[0] | anybad[1]);
}

// ---------------- degree count (2 edges/thread, vector loads) ----------------
__global__ void k_deg_count(const void* __restrict__ eiv) {
    int t = blockIdx.x * blockDim.x + threadIdx.x;
    int e = t * 2;
    if (e >= EE) return;
    int d0, d1;
    if (g_w64) {
        ulonglong2 p = *(const ulonglong2*)((const unsigned long long*)eiv + EE + e);
        d0 = (int)p.x; d1 = (int)p.y;
    } else {
        int2 p = *(const int2*)((const int*)eiv + EE + e);
        d0 = p.x; d1 = p.y;
    }
    atomicAdd(&g_degi[d0], 1);
    atomicAdd(&g_degi[d1], 1);
}

// ---------------- scan1 (+ dinv/selfc fused) ----------------
__global__ void k_scan1() {
    __shared__ int sm[256];
    int i = blockIdx.x * 256 + threadIdx.x;
    int v = (i < NN) ? g_degi[i] : 0;
    if (i < NN) {
        float deg = (float)(v + 1);        // + self-loop
        g_dinv[i]  = rsqrtf(deg);
        g_selfc[i] = OMA / deg;
    }
    sm[threadIdx.x] = v;
    __syncthreads();
#pragma unroll
    for (int off = 1; off < 256; off <<= 1) {
        int t = (threadIdx.x >= off) ? sm[threadIdx.x - off] : 0;
        __syncthreads();
        sm[threadIdx.x] += t;
        __syncthreads();
    }
    if (i < NN) g_ptr[i] = sm[threadIdx.x] - v;
    if (threadIdx.x == 255) g_bsum[blockIdx.x] = sm[255];
}

__global__ void k_scan2() {
    __shared__ int sm[512];
    int t = threadIdx.x;
    sm[t] = (t < SCAN_B) ? g_bsum[t] : 0;
    __syncthreads();
#pragma unroll
    for (int off = 1; off < 512; off <<= 1) {
        int v = (t >= off) ? sm[t - off] : 0;
        __syncthreads();
        sm[t] += v;
        __syncthreads();
    }
    if (t < SCAN_B) g_boff[t] = sm[t] - g_bsum[t];
}

__global__ void k_scan3() {
    int i = blockIdx.x * 256 + threadIdx.x;
    if (i < NN) {
        int p = g_ptr[i] + g_boff[blockIdx.x];
        g_ptr[i] = p;
        g_cursor[i] = p;
        g_degi[i] = 0;        // self-clean for the next call
    }
    if (i == 0) g_ptr[NN] = EE;
}

// ---------------- CSR fill (2 edges/thread, half2(w,w) weight) ----------------
__global__ void k_fill(const void* __restrict__ eiv) {
    int t = blockIdx.x * blockDim.x + threadIdx.x;
    int e = t * 2;
    if (e >= EE) return;
    int s0, s1, d0, d1;
    if (g_w64) {
        const unsigned long long* p = (const unsigned long long*)eiv;
        ulonglong2 sp = *(const ulonglong2*)(p + e);
        ulonglong2 dp = *(const ulonglong2*)(p + EE + e);
        s0 = (int)sp.x; s1 = (int)sp.y;
        d0 = (int)dp.x; d1 = (int)dp.y;
    } else {
        const int* p = (const int*)eiv;
        int2 sp = *(const int2*)(p + e);
        int2 dp = *(const int2*)(p + EE + e);
        s0 = sp.x; s1 = sp.y;
        d0 = dp.x; d1 = dp.y;
    }
    int pos0 = atomicAdd(&g_cursor[d0], 1);
    __half2 w0 = __float2half2_rn(OMA * g_dinv[s0] * g_dinv[d0]);
    g_csr[pos0] = make_int2(s0, *(int*)&w0);
    int pos1 = atomicAdd(&g_cursor[d1], 1);
    __half2 w1 = __float2half2_rn(OMA * g_dinv[s1] * g_dinv[d1]);
    g_csr[pos1] = make_int2(s1, *(int*)&w1);
}

// ---------------- common mma helpers ----------------
__device__ __forceinline__ unsigned bf2(float lo, float hi) {
    unsigned r;
    asm("cvt.rn.bf16x2.f32 %0, %1, %2;" : "=r"(r) : "f"(hi), "f"(lo));
    return r;
}
__device__ __forceinline__ uint32_t smem_u32(const void* p) {
    uint32_t a;
    asm("{ .reg .u64 t; cvta.to.shared.u64 t, %1; cvt.u32.u64 %0, t; }" : "=r"(a) : "l"(p));
    return a;
}
__device__ __forceinline__ void ldm_x4(uint32_t& r0, uint32_t& r1, uint32_t& r2, uint32_t& r3,
                                       uint32_t addr) {
    asm volatile("ldmatrix.sync.aligned.m8n8.x4.shared.b16 {%0,%1,%2,%3}, [%4];"
                 : "=r"(r0), "=r"(r1), "=r"(r2), "=r"(r3) : "r"(addr));
}
__device__ __forceinline__ void ldm_x4_t(uint32_t& r0, uint32_t& r1, uint32_t& r2, uint32_t& r3,
                                         uint32_t addr) {
    asm volatile("ldmatrix.sync.aligned.m8n8.x4.trans.shared.b16 {%0,%1,%2,%3}, [%4];"
                 : "=r"(r0), "=r"(r1), "=r"(r2), "=r"(r3) : "r"(addr));
}
__device__ __forceinline__ void ldm_x2_t(uint32_t& r0, uint32_t& r1, uint32_t addr) {
    asm volatile("ldmatrix.sync.aligned.m8n8.x2.trans.shared.b16 {%0,%1}, [%2];"
                 : "=r"(r0), "=r"(r1) : "r"(addr));
}
__device__ __forceinline__ void mma_bf16(float c[4], const uint32_t a[4], const uint32_t b[2]) {
    asm("mma.sync.aligned.m16n8k16.row.col.f32.bf16.bf16.f32 "
        "{%0,%1,%2,%3}, {%4,%5,%6,%7}, {%8,%9}, {%0,%1,%2,%3};"
        : "+f"(c[0]), "+f"(c[1]), "+f"(c[2]), "+f"(c[3])
        : "r"(a[0]), "r"(a[1]), "r"(a[2]), "r"(a[3]), "r"(b[0]), "r"(b[1]));
}
__device__ __forceinline__ void mma_f16(float c[4], const uint32_t a[4], const uint32_t b[2]) {
    asm("mma.sync.aligned.m16n8k16.row.col.f32.f16.f16.f32 "
        "{%0,%1,%2,%3}, {%4,%5,%6,%7}, {%8,%9}, {%0,%1,%2,%3};"
        : "+f"(c[0]), "+f"(c[1]), "+f"(c[2]), "+f"(c[3])
        : "r"(a[0]), "r"(a[1]), "r"(a[2]), "r"(a[3]), "r"(b[0]), "r"(b[1]));
}
__device__ __forceinline__ void hfma2(unsigned& acc, unsigned a, unsigned b) {
    asm("fma.rn.f16x2 %0, %1, %2, %0;" : "+r"(acc) : "r"(a), "r"(b));
}

// ---------------- GEMM1 (bf16 mma, double-buffered) -> fp16 h1 ----------------
__global__ void k_gemm1(const float* __restrict__ x,
                        const float* __restrict__ W1,
                        const float* __restrict__ b1) {
    __shared__ uint4 As4[2][512];
    __shared__ uint4 Bs4[2][256];
    __shared__ float b1s[64];
    const int tid  = threadIdx.x;
    const int lane = tid & 31;
    const int wid  = tid >> 5;
    const int wm   = wid >> 1;
    const int wn   = wid & 1;
    const int g    = lane >> 2;
    const int kt   = lane & 3;
    const int r0   = blockIdx.x * 128;
    if (tid < 64) b1s[tid] = b1[tid];

    const int amA[2]  = { (tid * 2) >> 2, (tid * 2 + 1) >> 2 };
    const int accA[2] = { (tid * 2) & 3,  (tid * 2 + 1) & 3 };
    const int bk  = tid >> 3;
    const int bcc = tid & 7;

    float c[2][4][4];
#pragma unroll
    for (int mt = 0; mt < 2; mt++)
#pragma unroll
        for (int nt = 0; nt < 4; nt++)
#pragma unroll
            for (int i = 0; i < 4; i++) c[mt][nt][i] = 0.0f;

    float4 pa[2][2];
    float4 pb[2];

    auto load_chunk = [&](int kb) {
#pragma unroll
        for (int j = 0; j < 2; j++) {
            int gr = r0 + amA[j];
            int gk = kb + accA[j] * 8;
            pa[j][0] = make_float4(0.f, 0.f, 0.f, 0.f);
            pa[j][1] = make_float4(0.f, 0.f, 0.f, 0.f);
            if (gr < NN) {
                const float* xp = &x[(size_t)gr * FF + gk];
                if (gk + 4 <= FF) pa[j][0] = *(const float4*)xp;
                if (gk + 8 <= FF) pa[j][1] = *(const float4*)(xp + 4);
            }
        }
        int gk = kb + bk;
        pb[0] = make_float4(0.f, 0.f, 0.f, 0.f);
        pb[1] = make_float4(0.f, 0.f, 0.f, 0.f);
        if (gk < FF) {
            const float* wp = &W1[(size_t)gk * HH + bcc * 8];
            pb[0] = *(const float4*)wp;
            pb[1] = *(const float4*)(wp + 4);
        }
    };
    auto store_chunk = [&](int buf) {
#pragma unroll
        for (int j = 0; j < 2; j++) {
            uint4 u;
            u.x = bf2(pa[j][0].x, pa[j][0].y);
            u.y = bf2(pa[j][0].z, pa[j][0].w);
            u.z = bf2(pa[j][1].x, pa[j][1].y);
            u.w = bf2(pa[j][1].z, pa[j][1].w);
            As4[buf][amA[j] * 4 + (accA[j] ^ ((amA[j] >> 1) & 3))] = u;
        }
        uint4 u;
        u.x = bf2(pb[0].x, pb[0].y);
        u.y = bf2(pb[0].z, pb[0].w);
        u.z = bf2(pb[1].x, pb[1].y);
        u.w = bf2(pb[1].z, pb[1].w);
        Bs4[buf][bk * 8 + (bcc ^ (bk & 7))] = u;
    };

    load_chunk(0);
    store_chunk(0);
    __syncthreads();

    for (int kb = 0; kb < 512; kb += 32) {
        const int buf = (kb >> 5) & 1;
        const bool has_next = (kb + 32 < 512);
        if (has_next) load_chunk(kb + 32);

        const uint32_t As_base = smem_u32(As4[buf]);
        const uint32_t Bs_base = smem_u32(Bs4[buf]);
#pragma unroll
        for (int ks = 0; ks < 32; ks += 16) {
            uint32_t a[2][4];
#pragma unroll
            for (int mt = 0; mt < 2; mt++) {
                int m  = wm * 32 + mt * 16 + (lane & 15);
                int cA = (ks >> 3) + (lane >> 4);
                uint32_t addr = As_base + m * 64 + ((cA ^ ((m >> 1) & 3)) << 4);
                ldm_x4(a[mt][0], a[mt][1], a[mt][2], a[mt][3], addr);
            }
            uint32_t b[4][2];
#pragma unroll
            for (int p = 0; p < 2; p++) {
                int k  = ks + (lane & 15);
                int cB = wn * 4 + 2 * p + (lane >> 4);
                uint32_t addr = Bs_base + k * 128 + ((cB ^ (k & 7)) << 4);
                ldm_x4_t(b[2 * p][0], b[2 * p][1], b[2 * p + 1][0], b[2 * p + 1][1], addr);
            }
#pragma unroll
            for (int mt = 0; mt < 2; mt++)
#pragma unroll
                for (int nt = 0; nt < 4; nt++)
                    mma_bf16(c[mt][nt], a[mt], b[nt]);
        }
        if (has_next) {
            store_chunk(buf ^ 1);
            __syncthreads();
        }
    }
#pragma unroll
    for (int mt = 0; mt < 2; mt++) {
        int row = r0 + wm * 32 + mt * 16 + g;
#pragma unroll
        for (int nt = 0; nt < 4; nt++) {
            int col = wn * 32 + nt * 8 + 2 * kt;
            if (row < NN) {
                __half2 v = __float22half2_rn(make_float2(fmaxf(c[mt][nt][0] + b1s[col], 0.f),
                                                          fmaxf(c[mt][nt][1] + b1s[col + 1], 0.f)));
                *(__half2*)&g_h1h[(size_t)row * HH + col] = v;
            }
            if (row + 8 < NN) {
                __half2 v = __float22half2_rn(make_float2(fmaxf(c[mt][nt][2] + b1s[col], 0.f),
                                                          fmaxf(c[mt][nt][3] + b1s[col + 1], 0.f)));
                *(__half2*)&g_h1h[(size_t)(row + 8) * HH + col] = v;
            }
        }
    }
}

// ---------------- GEMM2 (fp16 tensor cores) -> h16A + h0 ----------------
__global__ void k_gemm2(const float* __restrict__ W2,
                        const float* __restrict__ b2) {
    __shared__ uint4  h1s4[1024];
    __shared__ __half Bs[64 * 40];
    __shared__ float  b2s[40];
    const int tid  = threadIdx.x;
    const int lane = tid & 31;
    const int wid  = tid >> 5;
    const int g    = lane >> 2;
    const int kt   = lane & 3;
    const int rb   = blockIdx.x * 128;

#pragma unroll
    for (int j = 0; j < 5; j++) {
        int idx = tid + j * 128;
        int k   = idx / 10;
        int cg  = idx % 10;
        float4 v = *(const float4*)&W2[(size_t)k * CC + cg * 4];
        __half2 h0 = __float22half2_rn(make_float2(v.x, v.y));
        __half2 h1 = __float22half2_rn(make_float2(v.z, v.w));
        uint2 u;
        u.x = *(unsigned*)&h0;
        u.y = *(unsigned*)&h1;
        *(uint2*)&Bs[k * 40 + cg * 4] = u;
    }
    if (tid < 40) b2s[tid] = b2[tid];

#pragma unroll
    for (int j = 0; j < 8; j++) {
        int idx = tid + j * 128;
        int r   = idx >> 3;
        int cc  = idx & 7;
        int gr  = rb + r;
        uint4 v = make_uint4(0, 0, 0, 0);
        if (gr < NN) v = *(const uint4*)&g_h1h[(size_t)gr * HH + cc * 8];
        h1s4[r * 8 + (cc ^ (r & 7))] = v;
    }
    __syncthreads();

    const uint32_t A_base = smem_u32(h1s4);
    const uint32_t B_base = smem_u32(Bs);

    float c[2][5][4];
#pragma unroll
    for (int mt = 0; mt < 2; mt++)
#pragma unroll
        for (int nt = 0; nt < 5; nt++)
#pragma unroll
            for (int i = 0; i < 4; i++) c[mt][nt][i] = 0.0f;

#pragma unroll
    for (int ks = 0; ks < 64; ks += 16) {
        uint32_t a[2][4];
#pragma unroll
        for (int mt = 0; mt < 2; mt++) {
            int m  = wid * 32 + mt * 16 + (lane & 15);
            int cA = (ks >> 3) + (lane >> 4);
            uint32_t addr = A_base + m * 128 + ((cA ^ (m & 7)) << 4);
            ldm_x4(a[mt][0], a[mt][1], a[mt][2], a[mt][3], addr);
        }
        uint32_t b[5][2];
#pragma unroll
        for (int p = 0; p < 2; p++) {
            int k = ks + (lane & 15);
            int n = 2 * p * 8 + (lane >> 4) * 8;
            uint32_t addr = B_base + (k * 40 + n) * 2;
            ldm_x4_t(b[2 * p][0], b[2 * p][1], b[2 * p + 1][0], b[2 * p + 1][1], addr);
        }
        {
            int k = ks + (lane & 15);
            uint32_t addr = B_base + (k * 40 + 32) * 2;
            ldm_x2_t(b[4][0], b[4][1], addr);
        }
#pragma unroll
        for (int mt = 0; mt < 2; mt++)
#pragma unroll
            for (int nt = 0; nt < 5; nt++)
                mma_f16(c[mt][nt], a[mt], b[nt]);
    }

    float*   h0f  = (float*)g_h0;
    __half2* h16  = (__half2*)g_h16A;
#pragma unroll
    for (int mt = 0; mt < 2; mt++) {
        int row0 = rb + wid * 32 + mt * 16 + g;
#pragma unroll
        for (int nt = 0; nt < 5; nt++) {
            int col = nt * 8 + 2 * kt;
            float bx = b2s[col], by = b2s[col + 1];
            if (row0 < NN) {
                float2 v = make_float2(c[mt][nt][0] + bx, c[mt][nt][1] + by);
                *(float2*)&h0f[(size_t)row0 * CC + col] = v;
                h16[(size_t)row0 * 20 + col / 2] = __float22half2_rn(v);
            }
            if (row0 + 8 < NN) {
                float2 v = make_float2(c[mt][nt][2] + bx, c[mt][nt][3] + by);
                *(float2*)&h0f[(size_t)(row0 + 8) * CC + col] = v;
                h16[(size_t)(row0 + 8) * 20 + col / 2] = __float22half2_rn(v);
            }
        }
    }
}

// ---------------- propagation: HFMA2 blocks + cross-block 1-ahead prefetch (R13) ----------------
__global__ void k_prop(int parity) {
    const uint4* __restrict__ cur = parity ? g_h16B : g_h16A;
    uint4*       __restrict__ nw  = parity ? g_h16A : g_h16B;
    int wid = (blockIdx.x * blockDim.x + threadIdx.x) >> 5;
    if (wid >= NN) return;
    int lane = threadIdx.x & 31;
    int g    = lane / 5;          // 0..6 (6 => idle lanes 30,31)
    int c    = lane - g * 5;      // 0..4

    int beg = g_ptr[wid];
    int end = g_ptr[wid + 1];

    float f[8];
#pragma unroll
    for (int j = 0; j < 8; j++) f[j] = 0.f;

    if (g < 6) {
        int e = beg + g;
        if (e < end) {
            int2 sw = g_csr[e];       // prefetched current edge
            e += 6;
            bool done = false;
            while (!done) {
                // fp16 partial accumulators: at most 8 edges per flush block
                unsigned a0 = 0, a1 = 0, a2 = 0, a3 = 0;
#pragma unroll 1
                for (int it = 0; it < 8; it++) {
                    int2 nx;
                    bool more = (e < end);
                    if (more) nx = g_csr[e];     // prefetch next (flies over gather)
                    e += 6;
                    unsigned ww = (unsigned)sw.y;  // half2(w,w)
                    uint4 v = cur[(size_t)sw.x * 5 + c];
                    hfma2(a0, ww, v.x);
                    hfma2(a1, ww, v.y);
                    hfma2(a2, ww, v.z);
                    hfma2(a3, ww, v.w);
                    if (!more) { done = true; break; }
                    sw = nx;
                }
                // flush to fp32
                float2 p;
                p = __half22float2(*(__half2*)&a0); f[0] += p.x; f[1] += p.y;
                p = __half22float2(*(__half2*)&a1); f[2] += p.x; f[3] += p.y;
                p = __half22float2(*(__half2*)&a2); f[4] += p.x; f[5] += p.y;
                p = __half22float2(*(__half2*)&a3); f[6] += p.x; f[7] += p.y;
            }
        }
    }
    const unsigned FULL = 0xFFFFFFFFu;
#pragma unroll
    for (int j = 0; j < 8; j++) {
        float t = __shfl_down_sync(FULL, f[j], 15);
        f[j] += t;
        float t1 = __shfl_down_sync(FULL, f[j], 5);
        float t2 = __shfl_down_sync(FULL, f[j], 10);
        f[j] += t1 + t2;
    }

    if (lane < 5) {
        size_t idx = (size_t)wid * 5 + lane;
        float  sc  = g_selfc[wid];
        uint4  cs  = cur[idx];
        float4 h0a = g_h0[(size_t)wid * 10 + lane * 2 + 0];
        float4 h0b = g_h0[(size_t)wid * 10 + lane * 2 + 1];
        float2 q;
        q = __half22float2(*(__half2*)&cs.x);
        float r0 = f[0] + fmaf(sc, q.x, ALPHA * h0a.x);
        float r1 = f[1] + fmaf(sc, q.y, ALPHA * h0a.y);
        q = __half22float2(*(__half2*)&cs.y);
        float r2 = f[2] + fmaf(sc, q.x, ALPHA * h0a.z);
        float r3 = f[3] + fmaf(sc, q.y, ALPHA * h0a.w);
        q = __half22float2(*(__half2*)&cs.z);
        float r4 = f[4] + fmaf(sc, q.x, ALPHA * h0b.x);
        float r5 = f[5] + fmaf(sc, q.y, ALPHA * h0b.y);
        q = __half22float2(*(__half2*)&cs.w);
        float r6 = f[6] + fmaf(sc, q.x, ALPHA * h0b.z);
        float r7 = f[7] + fmaf(sc, q.y, ALPHA * h0b.w);
        __half2 p0 = __float22half2_rn(make_float2(r0, r1));
        __half2 p1 = __float22half2_rn(make_float2(r2, r3));
        __half2 p2 = __float22half2_rn(make_float2(r4, r5));
        __half2 p3 = __float22half2_rn(make_float2(r6, r7));
        uint4 u;
        u.x = *(unsigned*)&p0; u.y = *(unsigned*)&p1;
        u.z = *(unsigned*)&p2; u.w = *(unsigned*)&p3;
        nw[idx] = u;
    }
}

// ---------------- log_softmax over C=40 (fp16 input), warp per row ----------------
__global__ void k_logsoftmax(float* __restrict__ out) {
    int warp = threadIdx.x >> 5;
    int lane = threadIdx.x & 31;
    int row  = blockIdx.x * 4 + warp;
    if (row >= NN) return;
    const __half2* h = (const __half2*)g_h16A + (size_t)row * 20;
    float2 p = make_float2(-INFINITY, -INFINITY);
    if (lane < 20) p = __half22float2(h[lane]);
    float m = fmaxf(p.x, p.y);
#pragma unroll
    for (int off = 16; off > 0; off >>= 1)
        m = fmaxf(m, __shfl_xor_sync(0xFFFFFFFFu, m, off));
    float s = (lane < 20) ? (expf(p.x - m) + expf(p.y - m)) : 0.0f;
#pragma unroll
    for (int off = 16; off > 0; off >>= 1)
        s += __shfl_xor_sync(0xFFFFFFFFu, s, off);
    float ls = logf(s);
    if (lane < 20) {
        out[(size_t)row * CC + lane * 2 + 0] = p.x - m - ls;
        out[(size_t)row * CC + lane * 2 + 1] = p.y - m - ls;
    }
}

// ---------------- launch ----------------
extern "C" void kernel_launch(void* const* d_in, const int* in_sizes, int n_in,
                              void* d_out, int out_size) {
    const float* x  = (const float*)d_in[0];
    const float* W1 = (const float*)d_in[1];
    const float* b1 = (const float*)d_in[2];
    const float* W2 = (const float*)d_in[3];
    const float* b2 = (const float*)d_in[4];
    const void*  ei = d_in[5];
    float* out = (float*)d_out;

    const int TB  = 256;
    const int gE2 = (EE / 2 + TB - 1) / TB;   // 6250 (2 edges/thread)
    const int gP  = (NN + 7) / 8;             // 8 warps per block

    // g_degi enters every call zeroed (module init / k_scan3 self-clean).
    k_sniff<<<1, 64>>>((const unsigned long long*)ei);        // 0
    k_deg_count<<<gE2, TB>>>(ei);                             // 1
    k_scan1<<<SCAN_B, 256>>>();                               // 2
    k_gemm1<<<(NN + 127) / 128, 256>>>(x, W1, b1);            // 3 (profiled)
    k_scan2<<<1, 512>>>();
    k_scan3<<<SCAN_B, 256>>>();
    k_fill<<<gE2, TB>>>(ei);
    k_gemm2<<<(NN + 127) / 128, 128>>>(W2, b2);

    // K=10 propagation steps (ping-pong; final lands in h16A)
    for (int k = 0; k < 10; k++)
        k_prop<<<gP, TB>>>(k & 1);

    // output
    k_logsoftmax<<<(NN + 3) / 4, 128>>>(out);
}

// round 16
// speedup vs baseline: 1.1046x; 1.0102x over previous
#include <cuda_runtime.h>
#include <cuda_fp16.h>
#include <math.h>
#include <stdint.h>

// Problem shape (fixed by setup_inputs)
constexpr int   NN = 100000;
constexpr int   FF = 500;
constexpr int   HH = 64;
constexpr int   CC = 40;
constexpr int   EE = 3200000;
constexpr float ALPHA = 0.1f;
constexpr float OMA   = 0.9f;   // 1 - alpha
constexpr int   SCAN_B = (NN + 255) / 256;  // 391 scan blocks
constexpr int   RP = 8;         // h16 row pitch in uint4 (128B line-aligned; 5 used)

// ---- scratch (static __device__ arrays; zero-initialized at module load) ----
__device__ int     g_w64;           // 1 if edge_index is int64, 0 if int32
__device__ int     g_degi[NN];      // ALWAYS zero at kernel_launch entry
                                    // (module-load init; k_scan3 self-cleans)
__device__ float   g_dinv[NN];
__device__ float   g_selfc[NN];
__device__ int     g_ptr[NN + 1];   // CSR row pointers (by dst)
__device__ int     g_cursor[NN];
__device__ int     g_bsum[SCAN_B];
__device__ int     g_boff[SCAN_B];
__device__ int2    g_csr[EE];       // (src, half2(w,w) bits)
__device__ __half  g_h1h[(size_t)NN * HH];     // fp16 hidden
__device__ float4  g_h0[(size_t)NN * 10];      // fp32 teleport anchor
__device__ uint4   g_h16A[(size_t)NN * RP];    // fp16 h, 128B-padded rows
__device__ uint4   g_h16B[(size_t)NN * RP];

// ---------------- dtype sniff (1 block, 64 probes) ----------------
__global__ void k_sniff(const unsigned long long* __restrict__ ei) {
    __shared__ int anybad[2];
    unsigned long long v = ei[threadIdx.x];
    unsigned bad = __ballot_sync(0xFFFFFFFFu, v >= (unsigned long long)NN);
    anybad[threadIdx.x >> 5] = 0;
    __syncwarp();
    if (bad) anybad[threadIdx.x >> 5] = 1;
    __syncthreads();
    if (threadIdx.x == 0) g_w64 = !(anybad[0] | anybad[1]);
}

// ---------------- degree count (2 edges/thread, vector loads) ----------------
__global__ void k_deg_count(const void* __restrict__ eiv) {
    int t = blockIdx.x * blockDim.x + threadIdx.x;
    int e = t * 2;
    if (e >= EE) return;
    int d0, d1;
    if (g_w64) {
        ulonglong2 p = *(const ulonglong2*)((const unsigned long long*)eiv + EE + e);
        d0 = (int)p.x; d1 = (int)p.y;
    } else {
        int2 p = *(const int2*)((const int*)eiv + EE + e);
        d0 = p.x; d1 = p.y;
    }
    atomicAdd(&g_degi[d0], 1);
    atomicAdd(&g_degi[d1], 1);
}

// ---------------- scan1 (+ dinv/selfc fused) ----------------
__global__ void k_scan1() {
    __shared__ int sm[256];
    int i = blockIdx.x * 256 + threadIdx.x;
    int v = (i < NN) ? g_degi[i] : 0;
    if (i < NN) {
        float deg = (float)(v + 1);        // + self-loop
        g_dinv[i]  = rsqrtf(deg);
        g_selfc[i] = OMA / deg;
    }
    sm[threadIdx.x] = v;
    __syncthreads();
#pragma unroll
    for (int off = 1; off < 256; off <<= 1) {
        int t = (threadIdx.x >= off) ? sm[threadIdx.x - off] : 0;
        __syncthreads();
        sm[threadIdx.x] += t;
        __syncthreads();
    }
    if (i < NN) g_ptr[i] = sm[threadIdx.x] - v;
    if (threadIdx.x == 255) g_bsum[blockIdx.x] = sm[255];
}

__global__ void k_scan2() {
    __shared__ int sm[512];
    int t = threadIdx.x;
    sm[t] = (t < SCAN_B) ? g_bsum[t] : 0;
    __syncthreads();
#pragma unroll
    for (int off = 1; off < 512; off <<= 1) {
        int v = (t >= off) ? sm[t - off] : 0;
        __syncthreads();
        sm[t] += v;
        __syncthreads();
    }
    if (t < SCAN_B) g_boff[t] = sm[t] - g_bsum[t];
}

__global__ void k_scan3() {
    int i = blockIdx.x * 256 + threadIdx.x;
    if (i < NN) {
        int p = g_ptr[i] + g_boff[blockIdx.x];
        g_ptr[i] = p;
        g_cursor[i] = p;
        g_degi[i] = 0;        // self-clean for the next call
    }
    if (i == 0) g_ptr[NN] = EE;
}

// ---------------- CSR fill (2 edges/thread, half2(w,w) weight) ----------------
__global__ void k_fill(const void* __restrict__ eiv) {
    int t = blockIdx.x * blockDim.x + threadIdx.x;
    int e = t * 2;
    if (e >= EE) return;
    int s0, s1, d0, d1;
    if (g_w64) {
        const unsigned long long* p = (const unsigned long long*)eiv;
        ulonglong2 sp = *(const ulonglong2*)(p + e);
        ulonglong2 dp = *(const ulonglong2*)(p + EE + e);
        s0 = (int)sp.x; s1 = (int)sp.y;
        d0 = (int)dp.x; d1 = (int)dp.y;
    } else {
        const int* p = (const int*)eiv;
        int2 sp = *(const int2*)(p + e);
        int2 dp = *(const int2*)(p + EE + e);
        s0 = sp.x; s1 = sp.y;
        d0 = dp.x; d1 = dp.y;
    }
    int pos0 = atomicAdd(&g_cursor[d0], 1);
    __half2 w0 = __float2half2_rn(OMA * g_dinv[s0] * g_dinv[d0]);
    g_csr[pos0] = make_int2(s0, *(int*)&w0);
    int pos1 = atomicAdd(&g_cursor[d1], 1);
    __half2 w1 = __float2half2_rn(OMA * g_dinv[s1] * g_dinv[d1]);
    g_csr[pos1] = make_int2(s1, *(int*)&w1);
}

// ---------------- common mma helpers ----------------
__device__ __forceinline__ unsigned bf2(float lo, float hi) {
    unsigned r;
    asm("cvt.rn.bf16x2.f32 %0, %1, %2;" : "=r"(r) : "f"(hi), "f"(lo));
    return r;
}
__device__ __forceinline__ uint32_t smem_u32(const void* p) {
    uint32_t a;
    asm("{ .reg .u64 t; cvta.to.shared.u64 t, %1; cvt.u32.u64 %0, t; }" : "=r"(a) : "l"(p));
    return a;
}
__device__ __forceinline__ void ldm_x4(uint32_t& r0, uint32_t& r1, uint32_t& r2, uint32_t& r3,
                                       uint32_t addr) {
    asm volatile("ldmatrix.sync.aligned.m8n8.x4.shared.b16 {%0,%1,%2,%3}, [%4];"
                 : "=r"(r0), "=r"(r1), "=r"(r2), "=r"(r3) : "r"(addr));
}
__device__ __forceinline__ void ldm_x4_t(uint32_t& r0, uint32_t& r1, uint32_t& r2, uint32_t& r3,
                                         uint32_t addr) {
    asm volatile("ldmatrix.sync.aligned.m8n8.x4.trans.shared.b16 {%0,%1,%2,%3}, [%4];"
                 : "=r"(r0), "=r"(r1), "=r"(r2), "=r"(r3) : "r"(addr));
}
__device__ __forceinline__ void ldm_x2_t(uint32_t& r0, uint32_t& r1, uint32_t addr) {
    asm volatile("ldmatrix.sync.aligned.m8n8.x2.trans.shared.b16 {%0,%1}, [%2];"
                 : "=r"(r0), "=r"(r1) : "r"(addr));
}
__device__ __forceinline__ void mma_bf16(float c[4], const uint32_t a[4], const uint32_t b[2]) {
    asm("mma.sync.aligned.m16n8k16.row.col.f32.bf16.bf16.f32 "
        "{%0,%1,%2,%3}, {%4,%5,%6,%7}, {%8,%9}, {%0,%1,%2,%3};"
        : "+f"(c[0]), "+f"(c[1]), "+f"(c[2]), "+f"(c[3])
        : "r"(a[0]), "r"(a[1]), "r"(a[2]), "r"(a[3]), "r"(b[0]), "r"(b[1]));
}
__device__ __forceinline__ void mma_f16(float c[4], const uint32_t a[4], const uint32_t b[2]) {
    asm("mma.sync.aligned.m16n8k16.row.col.f32.f16.f16.f32 "
        "{%0,%1,%2,%3}, {%4,%5,%6,%7}, {%8,%9}, {%0,%1,%2,%3};"
        : "+f"(c[0]), "+f"(c[1]), "+f"(c[2]), "+f"(c[3])
        : "r"(a[0]), "r"(a[1]), "r"(a[2]), "r"(a[3]), "r"(b[0]), "r"(b[1]));
}
__device__ __forceinline__ void hfma2(unsigned& acc, unsigned a, unsigned b) {
    asm("fma.rn.f16x2 %0, %1, %2, %0;" : "+r"(acc) : "r"(a), "r"(b));
}

// ---------------- GEMM1 (bf16 mma, double-buffered, coalesced A-fill) -> fp16 h1 ----------------
// A-fill mapping: float4 index i = tid + p*256 (p<4); row = i>>3, c4 = i&7.
// 8 consecutive lanes load 128B contiguous from ONE row -> 4 line-tags per
// LDG.128 warp instruction (vs 16 with the old row-split mapping).
__global__ void k_gemm1(const float* __restrict__ x,
                        const float* __restrict__ W1,
                        const float* __restrict__ b1) {
    __shared__ uint4 As4[2][512];   // 128 rows * 4 chunks (uint4 = 8 bf16)
    __shared__ uint4 Bs4[2][256];   // 32 rows * 8 chunks
    __shared__ float b1s[64];
    const int tid  = threadIdx.x;
    const int lane = tid & 31;
    const int wid  = tid >> 5;
    const int wm   = wid >> 1;
    const int wn   = wid & 1;
    const int g    = lane >> 2;
    const int kt   = lane & 3;
    const int r0   = blockIdx.x * 128;
    if (tid < 64) b1s[tid] = b1[tid];

    // A-fill geometry: 4 float4s per thread
    int arow[4], ac4[4];
#pragma unroll
    for (int p = 0; p < 4; p++) {
        int i   = tid + p * 256;
        arow[p] = i >> 3;
        ac4[p]  = i & 7;
    }
    const int bk  = tid >> 3;
    const int bcc = tid & 7;

    float c[2][4][4];
#pragma unroll
    for (int mt = 0; mt < 2; mt++)
#pragma unroll
        for (int nt = 0; nt < 4; nt++)
#pragma unroll
            for (int i = 0; i < 4; i++) c[mt][nt][i] = 0.0f;

    float4 pa[4];
    float4 pb[2];

    auto load_chunk = [&](int kb) {
#pragma unroll
        for (int p = 0; p < 4; p++) {
            int gr = r0 + arow[p];
            int gk = kb + ac4[p] * 4;
            pa[p] = make_float4(0.f, 0.f, 0.f, 0.f);
            if (gr < NN && gk + 4 <= FF)
                pa[p] = *(const float4*)&x[(size_t)gr * FF + gk];
        }
        int gk = kb + bk;
        pb[0] = make_float4(0.f, 0.f, 0.f, 0.f);
        pb[1] = make_float4(0.f, 0.f, 0.f, 0.f);
        if (gk < FF) {
            const float* wp = &W1[(size_t)gk * HH + bcc * 8];
            pb[0] = *(const float4*)wp;
            pb[1] = *(const float4*)(wp + 4);
        }
    };
    auto store_chunk = [&](int buf) {
#pragma unroll
        for (int p = 0; p < 4; p++) {
            int row  = arow[p];
            int cc   = ac4[p] >> 1;        // 16-bf16 chunk
            int half = ac4[p] & 1;         // which 8B half
            uint2 u;
            u.x = bf2(pa[p].x, pa[p].y);
            u.y = bf2(pa[p].z, pa[p].w);
            char* base = (char*)&As4[buf][row * 4 + (cc ^ ((row >> 1) & 3))];
            *(uint2*)(base + half * 8) = u;
        }
        uint4 u;
        u.x = bf2(pb[0].x, pb[0].y);
        u.y = bf2(pb[0].z, pb[0].w);
        u.z = bf2(pb[1].x, pb[1].y);
        u.w = bf2(pb[1].z, pb[1].w);
        Bs4[buf][bk * 8 + (bcc ^ (bk & 7))] = u;
    };

    load_chunk(0);
    store_chunk(0);
    __syncthreads();

    for (int kb = 0; kb < 512; kb += 32) {
        const int buf = (kb >> 5) & 1;
        const bool has_next = (kb + 32 < 512);
        if (has_next) load_chunk(kb + 32);

        const uint32_t As_base = smem_u32(As4[buf]);
        const uint32_t Bs_base = smem_u32(Bs4[buf]);
#pragma unroll
        for (int ks = 0; ks < 32; ks += 16) {
            uint32_t a[2][4];
#pragma unroll
            for (int mt = 0; mt < 2; mt++) {
                int m  = wm * 32 + mt * 16 + (lane & 15);
                int cA = (ks >> 3) + (lane >> 4);
                uint32_t addr = As_base + m * 64 + ((cA ^ ((m >> 1) & 3)) << 4);
                ldm_x4(a[mt][0], a[mt][1], a[mt][2], a[mt][3], addr);
            }
            uint32_t b[4][2];
#pragma unroll
            for (int p = 0; p < 2; p++) {
                int k  = ks + (lane & 15);
                int cB = wn * 4 + 2 * p + (lane >> 4);
                uint32_t addr = Bs_base + k * 128 + ((cB ^ (k & 7)) << 4);
                ldm_x4_t(b[2 * p][0], b[2 * p][1], b[2 * p + 1][0], b[2 * p + 1][1], addr);
            }
#pragma unroll
            for (int mt = 0; mt < 2; mt++)
#pragma unroll
                for (int nt = 0; nt < 4; nt++)
                    mma_bf16(c[mt][nt], a[mt], b[nt]);
        }
        if (has_next) {
            store_chunk(buf ^ 1);
            __syncthreads();
        }
    }
#pragma unroll
    for (int mt = 0; mt < 2; mt++) {
        int row = r0 + wm * 32 + mt * 16 + g;
#pragma unroll
        for (int nt = 0; nt < 4; nt++) {
            int col = wn * 32 + nt * 8 + 2 * kt;
            if (row < NN) {
                __half2 v = __float22half2_rn(make_float2(fmaxf(c[mt][nt][0] + b1s[col], 0.f),
                                                          fmaxf(c[mt][nt][1] + b1s[col + 1], 0.f)));
                *(__half2*)&g_h1h[(size_t)row * HH + col] = v;
            }
            if (row + 8 < NN) {
                __half2 v = __float22half2_rn(make_float2(fmaxf(c[mt][nt][2] + b1s[col], 0.f),
                                                          fmaxf(c[mt][nt][3] + b1s[col + 1], 0.f)));
                *(__half2*)&g_h1h[(size_t)(row + 8) * HH + col] = v;
            }
        }
    }
}

// ---------------- GEMM2 (fp16 tensor cores) -> h16A (padded rows) + h0 ----------------
__global__ void k_gemm2(const float* __restrict__ W2,
                        const float* __restrict__ b2) {
    __shared__ uint4  h1s4[1024];
    __shared__ __half Bs[64 * 40];
    __shared__ float  b2s[40];
    const int tid  = threadIdx.x;
    const int lane = tid & 31;
    const int wid  = tid >> 5;
    const int g    = lane >> 2;
    const int kt   = lane & 3;
    const int rb   = blockIdx.x * 128;

#pragma unroll
    for (int j = 0; j < 5; j++) {
        int idx = tid + j * 128;
        int k   = idx / 10;
        int cg  = idx % 10;
        float4 v = *(const float4*)&W2[(size_t)k * CC + cg * 4];
        __half2 h0 = __float22half2_rn(make_float2(v.x, v.y));
        __half2 h1 = __float22half2_rn(make_float2(v.z, v.w));
        uint2 u;
        u.x = *(unsigned*)&h0;
        u.y = *(unsigned*)&h1;
        *(uint2*)&Bs[k * 40 + cg * 4] = u;
    }
    if (tid < 40) b2s[tid] = b2[tid];

#pragma unroll
    for (int j = 0; j < 8; j++) {
        int idx = tid + j * 128;
        int r   = idx >> 3;
        int cc  = idx & 7;
        int gr  = rb + r;
        uint4 v = make_uint4(0, 0, 0, 0);
        if (gr < NN) v = *(const uint4*)&g_h1h[(size_t)gr * HH + cc * 8];
        h1s4[r * 8 + (cc ^ (r & 7))] = v;
    }
    __syncthreads();

    const uint32_t A_base = smem_u32(h1s4);
    const uint32_t B_base = smem_u32(Bs);

    float c[2][5][4];
#pragma unroll
    for (int mt = 0; mt < 2; mt++)
#pragma unroll
        for (int nt = 0; nt < 5; nt++)
#pragma unroll
            for (int i = 0; i < 4; i++) c[mt][nt][i] = 0.0f;

#pragma unroll
    for (int ks = 0; ks < 64; ks += 16) {
        uint32_t a[2][4];
#pragma unroll
        for (int mt = 0; mt < 2; mt++) {
            int m  = wid * 32 + mt * 16 + (lane & 15);
            int cA = (ks >> 3) + (lane >> 4);
            uint32_t addr = A_base + m * 128 + ((cA ^ (m & 7)) << 4);
            ldm_x4(a[mt][0], a[mt][1], a[mt][2], a[mt][3], addr);
        }
        uint32_t b[5][2];
#pragma unroll
        for (int p = 0; p < 2; p++) {
            int k = ks + (lane & 15);
            int n = 2 * p * 8 + (lane >> 4) * 8;
            uint32_t addr = B_base + (k * 40 + n) * 2;
            ldm_x4_t(b[2 * p][0], b[2 * p][1], b[2 * p + 1][0], b[2 * p + 1][1], addr);
        }
        {
            int k = ks + (lane & 15);
            uint32_t addr = B_base + (k * 40 + 32) * 2;
            ldm_x2_t(b[4][0], b[4][1], addr);
        }
#pragma unroll
        for (int mt = 0; mt < 2; mt++)
#pragma unroll
            for (int nt = 0; nt < 5; nt++)
                mma_f16(c[mt][nt], a[mt], b[nt]);
    }

    float*   h0f  = (float*)g_h0;
    __half2* h16  = (__half2*)g_h16A;
#pragma unroll
    for (int mt = 0; mt < 2; mt++) {
        int row0 = rb + wid * 32 + mt * 16 + g;
#pragma unroll
        for (int nt = 0; nt < 5; nt++) {
            int col = nt * 8 + 2 * kt;
            float bx = b2s[col], by = b2s[col + 1];
            if (row0 < NN) {
                float2 v = make_float2(c[mt][nt][0] + bx, c[mt][nt][1] + by);
                *(float2*)&h0f[(size_t)row0 * CC + col] = v;
                h16[(size_t)row0 * (RP * 4) + col / 2] = __float22half2_rn(v);
            }
            if (row0 + 8 < NN) {
                float2 v = make_float2(c[mt][nt][2] + bx, c[mt][nt][3] + by);
                *(float2*)&h0f[(size_t)(row0 + 8) * CC + col] = v;
                h16[(size_t)(row0 + 8) * (RP * 4) + col / 2] = __float22half2_rn(v);
            }
        }
    }
}

// ---------------- propagation: HFMA2 blocks + 1-ahead prefetch, 128B rows ----------------
__global__ void k_prop(int parity) {
    const uint4* __restrict__ cur = parity ? g_h16B : g_h16A;
    uint4*       __restrict__ nw  = parity ? g_h16A : g_h16B;
    int wid = (blockIdx.x * blockDim.x + threadIdx.x) >> 5;
    if (wid >= NN) return;
    int lane = threadIdx.x & 31;
    int g    = lane / 5;          // 0..6 (6 => idle lanes 30,31)
    int c    = lane - g * 5;      // 0..4

    int beg = g_ptr[wid];
    int end = g_ptr[wid + 1];

    float f[8];
#pragma unroll
    for (int j = 0; j < 8; j++) f[j] = 0.f;

    if (g < 6) {
        int e = beg + g;
        if (e < end) {
            int2 sw = g_csr[e];       // prefetched current edge
            e += 6;
            bool done = false;
            while (!done) {
                // fp16 partial accumulators: at most 8 edges per flush block
                unsigned a0 = 0, a1 = 0, a2 = 0, a3 = 0;
#pragma unroll 1
                for (int it = 0; it < 8; it++) {
                    int2 nx;
                    bool more = (e < end);
                    if (more) nx = g_csr[e];     // prefetch next (flies over gather)
                    e += 6;
                    unsigned ww = (unsigned)sw.y;  // half2(w,w)
                    uint4 v = cur[(size_t)sw.x * RP + c];
                    hfma2(a0, ww, v.x);
                    hfma2(a1, ww, v.y);
                    hfma2(a2, ww, v.z);
                    hfma2(a3, ww, v.w);
                    if (!more) { done = true; break; }
                    sw = nx;
                }
                // flush to fp32
                float2 p;
                p = __half22float2(*(__half2*)&a0); f[0] += p.x; f[1] += p.y;
                p = __half22float2(*(__half2*)&a1); f[2] += p.x; f[3] += p.y;
                p = __half22float2(*(__half2*)&a2); f[4] += p.x; f[5] += p.y;
                p = __half22float2(*(__half2*)&a3); f[6] += p.x; f[7] += p.y;
            }
        }
    }
    const unsigned FULL = 0xFFFFFFFFu;
#pragma unroll
    for (int j = 0; j < 8; j++) {
        float t = __shfl_down_sync(FULL, f[j], 15);
        f[j] += t;
        float t1 = __shfl_down_sync(FULL, f[j], 5);
        float t2 = __shfl_down_sync(FULL, f[j], 10);
        f[j] += t1 + t2;
    }

    if (lane < 5) {
        size_t idx = (size_t)wid * RP + lane;
        float  sc  = g_selfc[wid];
        uint4  cs  = cur[idx];
        float4 h0a = g_h0[(size_t)wid * 10 + lane * 2 + 0];
        float4 h0b = g_h0[(size_t)wid * 10 + lane * 2 + 1];
        float2 q;
        q = __half22float2(*(__half2*)&cs.x);
        float r0 = f[0] + fmaf(sc, q.x, ALPHA * h0a.x);
        float r1 = f[1] + fmaf(sc, q.y, ALPHA * h0a.y);
        q = __half22float2(*(__half2*)&cs.y);
        float r2 = f[2] + fmaf(sc, q.x, ALPHA * h0a.z);
        float r3 = f[3] + fmaf(sc, q.y, ALPHA * h0a.w);
        q = __half22float2(*(__half2*)&cs.z);
        float r4 = f[4] + fmaf(sc, q.x, ALPHA * h0b.x);
        float r5 = f[5] + fmaf(sc, q.y, ALPHA * h0b.y);
        q = __half22float2(*(__half2*)&cs.w);
        float r6 = f[6] + fmaf(sc, q.x, ALPHA * h0b.z);
        float r7 = f[7] + fmaf(sc, q.y, ALPHA * h0b.w);
        __half2 p0 = __float22half2_rn(make_float2(r0, r1));
        __half2 p1 = __float22half2_rn(make_float2(r2, r3));
        __half2 p2 = __float22half2_rn(make_float2(r4, r5));
        __half2 p3 = __float22half2_rn(make_float2(r6, r7));
        uint4 u;
        u.x = *(unsigned*)&p0; u.y = *(unsigned*)&p1;
        u.z = *(unsigned*)&p2; u.w = *(unsigned*)&p3;
        nw[idx] = u;
    }
}

// ---------------- log_softmax over C=40 (fp16 input, padded rows), warp per row ----------------
__global__ void k_logsoftmax(float* __restrict__ out) {
    int warp = threadIdx.x >> 5;
    int lane = threadIdx.x & 31;
    int row  = blockIdx.x * 4 + warp;
    if (row >= NN) return;
    const __half2* h = (const __half2*)g_h16A + (size_t)row * (RP * 4);
    float2 p = make_float2(-INFINITY, -INFINITY);
    if (lane < 20) p = __half22float2(h[lane]);
    float m = fmaxf(p.x, p.y);
#pragma unroll
    for (int off = 16; off > 0; off >>= 1)
        m = fmaxf(m, __shfl_xor_sync(0xFFFFFFFFu, m, off));
    float s = (lane < 20) ? (expf(p.x - m) + expf(p.y - m)) : 0.0f;
#pragma unroll
    for (int off = 16; off > 0; off >>= 1)
        s += __shfl_xor_sync(0xFFFFFFFFu, s, off);
    float ls = logf(s);
    if (lane < 20) {
        out[(size_t)row * CC + lane * 2 + 0] = p.x - m - ls;
        out[(size_t)row * CC + lane * 2 + 1] = p.y - m - ls;
    }
}

// ---------------- launch ----------------
extern "C" void kernel_launch(void* const* d_in, const int* in_sizes, int n_in,
                              void* d_out, int out_size) {
    const float* x  = (const float*)d_in[0];
    const float* W1 = (const float*)d_in[1];
    const float* b1 = (const float*)d_in[2];
    const float* W2 = (const float*)d_in[3];
    const float* b2 = (const float*)d_in[4];
    const void*  ei = d_in[5];
    float* out = (float*)d_out;

    const int TB  = 256;
    const int gE2 = (EE / 2 + TB - 1) / TB;   // 6250 (2 edges/thread)
    const int gP  = (NN + 7) / 8;             // 8 warps per block

    // g_degi enters every call zeroed (module init / k_scan3 self-clean).
    k_sniff<<<1, 64>>>((const unsigned long long*)ei);        // 0
    k_deg_count<<<gE2, TB>>>(ei);                             // 1
    k_scan1<<<SCAN_B, 256>>>();                               // 2
    k_gemm1<<<(NN + 127) / 128, 256>>>(x, W1, b1);            // 3 (profiled)
    k_scan2<<<1, 512>>>();
    k_scan3<<<SCAN_B, 256>>>();
    k_fill<<<gE2, TB>>>(ei);
    k_gemm2<<<(NN + 127) / 128, 128>>>(W2, b2);

    // K=10 propagation steps (ping-pong; final lands in h16A)
    for (int k = 0; k < 10; k++)
        k_prop<<<gP, TB>>>(k & 1);

    // output
    k_logsoftmax<<<(NN + 3) / 4, 128>>>(out);
}